// round 7
// baseline (speedup 1.0000x reference)
#include <cuda_runtime.h>

// YOLO postprocess: filter(score>0.5) -> sort desc -> greedy NMS(IoU>0.5) -> masked rows.
// x: (1, 84, 8400) f32 channel-major; out: (8400, 5) f32.
//
//   K0 filter (warp-aggregated compaction)
//   K1 rank-by-counting sort + gather (broadcast streaming, no syncs)
//   K2 sparse suppression edges (128x128 tiles, hit-mask accumulate) + predb
//   K3 exact greedy via seeded fixed-point + fused output + self-reset
//
// Greedy NMS == unique fixed point of:
//   j SUP  iff exists edge (i,j), i<j, i KEEP
//   j KEEP iff every edge (i,j) has i SUP
// Rows with no predecessor edge are KEEP immediately (seeded from predb).
// Each round the minimum-index unknown row settles => guaranteed convergence.

#define N_IN   8400
#define NSORT  8192
#define FULLW  0xffffffffu
#define ECAP   (1 << 20)       // edge capacity (4 MB scratch; ~25k expected)
#define ESM    32768           // edges cached in smem (128 KB)
#define NB32   256             // 8192 bits / 32

// ---------------- global scratch ----------------
__device__ int      g_cnt;          // zero at rest (reset by K3)
__device__ int      g_ecnt;         // zero at rest (reset by K3)
__device__ unsigned g_predb[NB32];  // zero at rest (reset by K3)
__device__ __align__(16) unsigned long long g_keys[NSORT];
__device__ __align__(16) float4 g_boxes[NSORT];
__device__ float    g_score[NSORT];
__device__ float    g_area[NSORT];
__device__ unsigned g_edges[ECAP];

// ---------------- K0: filter + compact (order canonicalized by K1) --------
extern "C" __global__ void __launch_bounds__(256)
k0_filter_kernel(const float* __restrict__ x)
{
    const int n = blockIdx.x * 256 + threadIdx.x;
    bool pass = false;
    float s = 0.f;
    if (n < N_IN) {
        s = x[4 * N_IN + n];
        pass = (s > 0.5f);
    }
    unsigned m = __ballot_sync(FULLW, pass);
    if (!m) return;
    int lane = threadIdx.x & 31;
    int leader = __ffs(m) - 1;
    int base = 0;
    if (lane == leader) base = atomicAdd(&g_cnt, __popc(m));
    base = __shfl_sync(FULLW, base, leader);
    if (pass) {
        int slot = base + __popc(m & ((1u << lane) - 1));
        if (slot < NSORT) {
            unsigned sb = __float_as_uint(s);
            g_keys[slot] = ((unsigned long long)(~sb) << 32) | (unsigned)n;
        }
    }
}

// ---------------- K1: rank-by-counting sort + gather ----------------------
// keys unique (idx in low bits) => rank is an exact permutation.
// key = (~score_bits)<<32 | idx : ascending == descending score, stable ties.
// All threads stream the same key sequence: L1 broadcast, no smem, no syncs.
extern "C" __global__ void __launch_bounds__(64)
k1_rank_kernel(const float* __restrict__ x)
{
    const int M = min(g_cnt, NSORT);
    if ((int)(blockIdx.x * 64) >= M) return;          // uniform block early-exit

    const int t = blockIdx.x * 64 + threadIdx.x;
    const unsigned long long mykey = (t < M) ? g_keys[t] : ~0ULL;
    const ulonglong2* kp = (const ulonglong2*)g_keys;

    int rank = 0;
    int k = 0;
    const int Mp = M >> 3 << 3;                        // multiple of 8
    for (; k < Mp; k += 8) {
        ulonglong2 a = __ldg(&kp[(k >> 1) + 0]);
        ulonglong2 b = __ldg(&kp[(k >> 1) + 1]);
        ulonglong2 c = __ldg(&kp[(k >> 1) + 2]);
        ulonglong2 d = __ldg(&kp[(k >> 1) + 3]);
        rank += (a.x < mykey) + (a.y < mykey)
              + (b.x < mykey) + (b.y < mykey)
              + (c.x < mykey) + (c.y < mykey)
              + (d.x < mykey) + (d.y < mykey);
    }
    for (; k < M; k++) rank += (g_keys[k] < mykey);

    if (t < M) {
        int idx = (int)(unsigned)mykey;
        float X1 = x[idx];
        float Y1 = x[N_IN + idx];
        float X2 = x[2 * N_IN + idx];
        float Y2 = x[3 * N_IN + idx];
        g_boxes[rank] = make_float4(X1, Y1, X2, Y2);
        g_score[rank] = __uint_as_float(~(unsigned)(mykey >> 32));
        g_area[rank]  = (X2 - X1) * (Y2 - Y1);
    }
}

// ---------------- K2: sparse edges, 128x128 tiles, hit-mask accumulate ----
// Thread = (row, col-half); inner loop over 64 columns is pure FP into a u64
// hit mask; index predicates applied as post-loop masks; warp-aggregated
// emission. Edge (i,j) packed (i<<13)|j when IoU>0.5:
//   IoU > 0.5 <=> 3*inter > area_i + area_j + 1e-9 (denominator always > 0).
#define NCT128 (NSORT / 128)                    // 64
#define K2_GRID (NCT128 * (NCT128 + 1) / 2)     // 2080

extern "C" __global__ void __launch_bounds__(256)
k2_edges_kernel()
{
    // linear -> (ty <= tx) triangle decode
    const int L = blockIdx.x;
    int tx = (int)((sqrtf(8.0f * (float)L + 1.0f) - 1.0f) * 0.5f);
    while ((tx + 1) * (tx + 2) / 2 <= L) tx++;
    while (tx * (tx + 1) / 2 > L) tx--;
    const int ty = L - tx * (tx + 1) / 2;

    const int M = min(g_cnt, NSORT);
    if ((ty << 7) >= M || (tx << 7) >= M) return;

    __shared__ float4 cb[128];
    __shared__ float  ca[128];
    const int t = threadIdx.x;
    const int j0t = tx << 7;
    if (t < 128) {
        int jg = j0t + t;
        if (jg < M) { cb[t] = g_boxes[jg]; ca[t] = g_area[jg]; }
        else        { cb[t] = make_float4(0, 0, 0, 0); ca[t] = 1e30f; }
    }
    __syncthreads();

    const int row = t >> 1, ch = t & 1;
    const int i   = (ty << 7) + row;
    const bool iv = i < M;
    float4 b = make_float4(0, 0, 0, 0);
    float sA = 0.f;
    if (iv) { b = g_boxes[i]; sA = g_area[i] + 1e-9f; }
    const int lc0 = ch << 6;           // local col base (0 or 64)
    const int jg0 = j0t + lc0;

    unsigned long long hits = 0;
#pragma unroll 8
    for (int c = 0; c < 64; c++) {
        float4 q = cb[lc0 + c];
        float iw = fminf(b.z, q.z) - fmaxf(b.x, q.x);
        float ih = fminf(b.w, q.w) - fmaxf(b.y, q.y);
        float inter = fmaxf(iw, 0.f) * fmaxf(ih, 0.f);
        if (3.0f * inter > sA + ca[lc0 + c]) hits |= 1ULL << c;
    }

    // post-loop masks: row valid, j > i, j < M
    if (!iv) hits = 0;
    {
        int d = i - jg0;               // need c > d
        unsigned long long mGT = (d < 0) ? ~0ULL
                               : (d >= 63 ? 0ULL : ~((1ULL << (d + 1)) - 1ULL));
        int nc = M - jg0;              // need c < nc
        unsigned long long mM  = (nc >= 64) ? ~0ULL
                               : (nc <= 0 ? 0ULL : ((1ULL << nc) - 1ULL));
        hits &= mGT & mM;
    }

    // warp-aggregated emission
    const int lane = t & 31;
    int cnt = __popcll(hits);
    int inc = cnt;
#pragma unroll
    for (int d = 1; d < 32; d <<= 1) {
        int v = __shfl_up_sync(FULLW, inc, d);
        if (lane >= d) inc += v;
    }
    int total = __shfl_sync(FULLW, inc, 31);
    if (total == 0) return;
    int base = 0;
    if (lane == 0) base = atomicAdd(&g_ecnt, total);
    base = __shfl_sync(FULLW, base, 0);
    int p = base + inc - cnt;
    while (hits) {
        int c = __ffsll((long long)hits) - 1;
        hits &= hits - 1;
        int j = jg0 + c;
        if (p < ECAP) g_edges[p] = ((unsigned)i << 13) | (unsigned)j;
        p++;
        atomicOr(&g_predb[j >> 5], 1u << (j & 31));
    }
}

// ---------------- K3: seeded fixed-point + fused output + self-reset ------
#define K3_SMEM (ESM * 4)     // 128 KB edge cache

extern "C" __global__ void __launch_bounds__(1024, 1)
k3_fixed_kernel(float* __restrict__ out)
{
    extern __shared__ unsigned se[];                  // [ESM]
    __shared__ unsigned keepb[NB32], supb[NB32], nsup[NB32], unkp[NB32];
    __shared__ int notdone;
    const int M   = min(g_cnt, NSORT);
    const int tid = threadIdx.x;
    int E = g_ecnt; if (E > ECAP) E = ECAP;
    const int Es = min(E, ESM);

    for (int e = tid; e < Es; e += 1024) se[e] = g_edges[e];
    if (tid < NB32) {
        int base = tid << 5;
        unsigned valid = (base + 32 <= M) ? 0xffffffffu
                       : (base >= M ? 0u : ((1u << (M - base)) - 1u));
        keepb[tid] = valid & ~g_predb[tid];   // no-pred rows are KEEP
        supb[tid]  = 0u;
    }
    __syncthreads();

    for (int round = 0; round < NSORT; round++) {
        if (tid < NB32) { nsup[tid] = 0u; unkp[tid] = 0u; }
        if (tid == 0) notdone = 0;
        __syncthreads();

        for (int e = tid; e < E; e += 1024) {
            unsigned ed = (e < ESM) ? se[e] : g_edges[e];
            int i = (int)(ed >> 13), j = (int)(ed & 8191u);
            unsigned jset = (keepb[j >> 5] | supb[j >> 5]) >> (j & 31);
            if (jset & 1u) continue;                          // j settled
            if ((keepb[i >> 5] >> (i & 31)) & 1u)
                atomicOr(&nsup[j >> 5], 1u << (j & 31));      // KEEP pred -> SUP
            else if (!((supb[i >> 5] >> (i & 31)) & 1u))
                atomicOr(&unkp[j >> 5], 1u << (j & 31));      // UNKNOWN pred
        }
        __syncthreads();

        if (tid < NB32) {
            int base = tid << 5;
            unsigned valid = (base + 32 <= M) ? 0xffffffffu
                           : (base >= M ? 0u : ((1u << (M - base)) - 1u));
            unsigned unk = ~(keepb[tid] | supb[tid]) & valid;
            if (unk) {
                unsigned ns = nsup[tid] & unk;
                unsigned nk = unk & ~nsup[tid] & ~unkp[tid];
                supb[tid]  |= ns;
                keepb[tid] |= nk;
                if (unk & ~(ns | nk)) notdone = 1;            // benign race
            }
        }
        __syncthreads();
        if (!notdone) break;
    }

    // fused masked output write
    for (int r = tid; r < N_IN; r += 1024) {
        if (r < M) {
            float m = (float)((keepb[r >> 5] >> (r & 31)) & 1u);
            float4 b = g_boxes[r];
            out[r * 5 + 0] = b.x * m;
            out[r * 5 + 1] = b.y * m;
            out[r * 5 + 2] = b.z * m;
            out[r * 5 + 3] = b.w * m;
            out[r * 5 + 4] = g_score[r] * m;
        } else {
            out[r * 5 + 0] = 0.f;
            out[r * 5 + 1] = 0.f;
            out[r * 5 + 2] = 0.f;
            out[r * 5 + 3] = 0.f;
            out[r * 5 + 4] = 0.f;
        }
    }

    // restore zero-invariants for next call / graph replay
    __syncthreads();
    if (tid < NB32) g_predb[tid] = 0u;
    if (tid == 0) { g_cnt = 0; g_ecnt = 0; }
}

// ---------------- launcher ----------------
extern "C" void kernel_launch(void* const* d_in, const int* in_sizes, int n_in,
                              void* d_out, int out_size)
{
    (void)in_sizes; (void)n_in; (void)out_size;
    const float* x = (const float*)d_in[0];
    float* out = (float*)d_out;

    static bool init_done = false;
    if (!init_done) {
        cudaFuncSetAttribute(k3_fixed_kernel,
                             cudaFuncAttributeMaxDynamicSharedMemorySize, K3_SMEM);
        init_done = true;
    }

    k0_filter_kernel<<<(N_IN + 255) / 256, 256>>>(x);
    k1_rank_kernel<<<NSORT / 64, 64>>>(x);
    k2_edges_kernel<<<K2_GRID, 256>>>();
    k3_fixed_kernel<<<1, 1024, K3_SMEM>>>(out);
}

// round 8
// speedup vs baseline: 1.6395x; 1.6395x over previous
#include <cuda_runtime.h>

// YOLO postprocess: filter(score>0.5) -> sort desc -> greedy NMS(IoU>0.5) -> masked rows.
// x: (1, 84, 8400) f32 channel-major; out: (8400, 5) f32.
//
//   K0 filter (warp-aggregated compaction)
//   K1 rank-by-counting sort + gather (smem tiles, chip-parallel)
//   K2 sparse suppression edge list (64x64 tiles, upper triangle)
//   K3 exact greedy via fixed-point propagation + fused output + self-reset
//
// Greedy NMS == unique fixed point of:
//   j SUP  iff exists edge (i,j), i<j, i KEEP
//   j KEEP iff every edge (i,j) has i SUP
// Each round the minimum-index unknown row settles => guaranteed convergence.

#define N_IN   8400
#define NSORT  8192
#define FULLW  0xffffffffu
#define ECAP   (1 << 20)      // edge capacity (4 MB scratch; ~25k expected)
#define ESM    40960          // edges cached in smem (160 KB)
#define NB32   256            // 8192 bits / 32

// ---------------- global scratch ----------------
__device__ int    g_cnt;      // zero at rest (reset by K3)
__device__ int    g_ecnt;     // zero at rest (reset by K3)
__device__ unsigned long long g_keys[NSORT];
__device__ __align__(16) float4 g_boxes[NSORT];
__device__ float  g_score[NSORT];
__device__ float  g_area[NSORT];
__device__ unsigned g_edges[ECAP];

// ---------------- K0: filter + compact (order canonicalized by K1) --------
extern "C" __global__ void __launch_bounds__(256)
k0_filter_kernel(const float* __restrict__ x)
{
    const int n = blockIdx.x * 256 + threadIdx.x;
    bool pass = false;
    float s = 0.f;
    if (n < N_IN) {
        s = x[4 * N_IN + n];
        pass = (s > 0.5f);
    }
    unsigned m = __ballot_sync(FULLW, pass);
    if (!m) return;
    int lane = threadIdx.x & 31;
    int leader = __ffs(m) - 1;
    int base = 0;
    if (lane == leader) base = atomicAdd(&g_cnt, __popc(m));
    base = __shfl_sync(FULLW, base, leader);
    if (pass) {
        int slot = base + __popc(m & ((1u << lane) - 1));
        if (slot < NSORT) {
            unsigned sb = __float_as_uint(s);
            g_keys[slot] = ((unsigned long long)(~sb) << 32) | (unsigned)n;
        }
    }
}

// ---------------- K1: rank-by-counting sort + gather ----------------------
// keys unique (idx in low bits) => rank is an exact permutation.
// key = (~score_bits)<<32 | idx : ascending == descending score, stable ties.
extern "C" __global__ void __launch_bounds__(64)
k1_rank_kernel(const float* __restrict__ x)
{
    __shared__ unsigned long long tile[64];
    const int M = min(g_cnt, NSORT);
    if ((int)(blockIdx.x * 64) >= M) return;          // uniform block early-exit

    const int t = blockIdx.x * 64 + threadIdx.x;
    unsigned long long mykey = (t < M) ? g_keys[t] : ~0ULL;
    int rank = 0;
    for (int base = 0; base < M; base += 64) {
        int c = base + threadIdx.x;
        tile[threadIdx.x] = (c < M) ? g_keys[c] : ~0ULL;  // sentinel never counts
        __syncthreads();
#pragma unroll 16
        for (int j = 0; j < 64; j++)
            rank += (tile[j] < mykey);
        __syncthreads();
    }

    if (t < M) {
        int idx = (int)(unsigned)mykey;
        float X1 = x[idx];
        float Y1 = x[N_IN + idx];
        float X2 = x[2 * N_IN + idx];
        float Y2 = x[3 * N_IN + idx];
        g_boxes[rank] = make_float4(X1, Y1, X2, Y2);
        g_score[rank] = __uint_as_float(~(unsigned)(mykey >> 32));
        g_area[rank]  = (X2 - X1) * (Y2 - Y1);
    }
}

// ---------------- K2: sparse suppression edges (64x64 tiles) --------------
// Edge (i, j), i<j, packed (i<<13)|j, when IoU>0.5:
//   IoU > 0.5 <=> 3*inter > area_i + area_j + 1e-9 (denominator always > 0).
extern "C" __global__ void __launch_bounds__(64)
k2_edges_kernel()
{
    const int bx = blockIdx.x, by = blockIdx.y;
    if (bx < by) return;
    const int M = min(g_cnt, NSORT);
    const int nct = (M + 63) >> 6;
    if (by >= nct || bx >= nct) return;

    __shared__ float4 cb[64];
    __shared__ float  ca[64];
    __shared__ unsigned ebuf[4096];     // worst case: full 64x64 tile
    __shared__ int ec, gbase;
    const int t  = threadIdx.x;
    if (t == 0) ec = 0;
    const int j0 = bx << 6;
    cb[t] = g_boxes[j0 + t];
    ca[t] = g_area[j0 + t];
    __syncthreads();

    const int i = (by << 6) + t;
    if (i < M) {
        const float4 b  = g_boxes[i];
        const float  sA = g_area[i] + 1e-9f;
        const int    nc = min(64, M - j0);
        const int    c0 = (bx == by) ? (t + 1) : 0;   // strict upper triangle
        for (int c = c0; c < nc; c++) {
            float4 q = cb[c];
            float iw = fminf(b.z, q.z) - fmaxf(b.x, q.x);
            float ih = fminf(b.w, q.w) - fmaxf(b.y, q.y);
            float inter = fmaxf(iw, 0.f) * fmaxf(ih, 0.f);
            if (3.0f * inter > sA + ca[c]) {
                int p = atomicAdd(&ec, 1);
                ebuf[p] = ((unsigned)i << 13) | (unsigned)(j0 + c);
            }
        }
    }
    __syncthreads();
    if (t == 0 && ec > 0) gbase = atomicAdd(&g_ecnt, ec);
    __syncthreads();
    for (int p = t; p < ec; p += 64) {
        int gp = gbase + p;
        if (gp < ECAP) g_edges[gp] = ebuf[p];
    }
}

// ---------------- K3: fixed-point propagation + fused output + reset ------
#define K3_SMEM (ESM * 4)     // 160 KB edge cache

extern "C" __global__ void __launch_bounds__(1024, 1)
k3_fixed_kernel(float* __restrict__ out)
{
    extern __shared__ unsigned se[];                  // [ESM]
    __shared__ unsigned keepb[NB32], supb[NB32], nsup[NB32], unkp[NB32];
    __shared__ int notdone;
    const int M   = min(g_cnt, NSORT);
    const int tid = threadIdx.x;
    int E = g_ecnt; if (E > ECAP) E = ECAP;
    const int Es = min(E, ESM);

    for (int e = tid; e < Es; e += 1024) se[e] = g_edges[e];
    if (tid < NB32) { keepb[tid] = 0u; supb[tid] = 0u; }
    __syncthreads();

    for (int round = 0; round < NSORT; round++) {
        if (tid < NB32) { nsup[tid] = 0u; unkp[tid] = 0u; }
        if (tid == 0) notdone = 0;
        __syncthreads();

        for (int e = tid; e < E; e += 1024) {
            unsigned ed = (e < ESM) ? se[e] : g_edges[e];
            int i = (int)(ed >> 13), j = (int)(ed & 8191u);
            unsigned jset = (keepb[j >> 5] | supb[j >> 5]) >> (j & 31);
            if (jset & 1u) continue;                          // j settled
            if ((keepb[i >> 5] >> (i & 31)) & 1u)
                atomicOr(&nsup[j >> 5], 1u << (j & 31));      // KEEP pred -> SUP
            else if (!((supb[i >> 5] >> (i & 31)) & 1u))
                atomicOr(&unkp[j >> 5], 1u << (j & 31));      // UNKNOWN pred
        }
        __syncthreads();

        if (tid < NB32) {
            int base = tid << 5;
            unsigned valid = (base + 32 <= M) ? 0xffffffffu
                           : (base >= M ? 0u : ((1u << (M - base)) - 1u));
            unsigned unk = ~(keepb[tid] | supb[tid]) & valid;
            if (unk) {
                unsigned ns = nsup[tid] & unk;
                unsigned nk = unk & ~nsup[tid] & ~unkp[tid];
                supb[tid]  |= ns;
                keepb[tid] |= nk;
                if (unk & ~(ns | nk)) notdone = 1;            // benign race
            }
        }
        __syncthreads();
        if (!notdone) break;
    }

    // fused masked output write (replaces separate K4 kernel)
    for (int r = tid; r < N_IN; r += 1024) {
        if (r < M) {
            float m = (float)((keepb[r >> 5] >> (r & 31)) & 1u);
            float4 b = g_boxes[r];
            out[r * 5 + 0] = b.x * m;
            out[r * 5 + 1] = b.y * m;
            out[r * 5 + 2] = b.z * m;
            out[r * 5 + 3] = b.w * m;
            out[r * 5 + 4] = g_score[r] * m;
        } else {
            out[r * 5 + 0] = 0.f;
            out[r * 5 + 1] = 0.f;
            out[r * 5 + 2] = 0.f;
            out[r * 5 + 3] = 0.f;
            out[r * 5 + 4] = 0.f;
        }
    }

    // restore zero-invariants for next call / graph replay (replaces memsets)
    __syncthreads();
    if (tid == 0) { g_cnt = 0; g_ecnt = 0; }
}

// ---------------- launcher ----------------
extern "C" void kernel_launch(void* const* d_in, const int* in_sizes, int n_in,
                              void* d_out, int out_size)
{
    (void)in_sizes; (void)n_in; (void)out_size;
    const float* x = (const float*)d_in[0];
    float* out = (float*)d_out;

    static bool init_done = false;
    if (!init_done) {
        cudaFuncSetAttribute(k3_fixed_kernel,
                             cudaFuncAttributeMaxDynamicSharedMemorySize, K3_SMEM);
        init_done = true;
    }

    k0_filter_kernel<<<(N_IN + 255) / 256, 256>>>(x);
    k1_rank_kernel<<<NSORT / 64, 64>>>(x);
    k2_edges_kernel<<<dim3(NSORT / 64, NSORT / 64), 64>>>();
    k3_fixed_kernel<<<1, 1024, K3_SMEM>>>(out);
}